// round 8
// baseline (speedup 1.0000x reference)
#include <cuda_runtime.h>

#define B 8
#define A 65536
#define C 80
#define G 16
#define TOPK 50
#define NBINS 8192
#define BSHIFT 17
#define FLOORBIN 7846          // __float_as_uint(0.05f) >> 17
#define CAP 8192               // per-bg candidate list capacity
#define SCAP 4096              // kS smem filtered capacity
#define KA_BLOCKS 2048
#define KN_BLOCKS 6144
#define KD_FB_BLOCKS 2048
#define KD_SP_BLOCKS 256

// ------------------------- static device scratch -------------------------
__device__ unsigned g_hist[(size_t)B * G * NBINS];       // 4.2 MB histograms
__device__ unsigned g_maxiou[B * G];                     // max decoded IoU (bits)
__device__ int      g_tbin[B * G];                       // threshold bin
__device__ float    g_invden[B * G];                     // 1/(t2-0.5) or 0
__device__ int      g_lcnt[B * G];                       // candidate list counts
__device__ unsigned long long g_list[(size_t)B * G * CAP]; // 8 MB candidate keys
__device__ int      g_fb[B * G];                         // fallback flag: 0/1/2
__device__ int      g_anyfb;                             // any fallback needed
__device__ int      g_nrec;                              // sparse record count
__device__ unsigned g_rec[B * A];                        // sparse records (b<<16 | a)
__device__ double   g_sums[2];                           // [0]=pos, [1]=neg

// ------------------------------ helpers ---------------------------------
// Bit-deterministic anchor-form IoU (explicit _rn so all kernels agree bitwise).
__device__ __forceinline__ float anchor_iou(const float4 p, const float4 t) {
    float ax0 = __fmaf_rn(-0.5f, p.z, p.x);
    float ay0 = __fmaf_rn(-0.5f, p.w, p.y);
    float ax1 = __fmaf_rn( 0.5f, p.z, p.x);
    float ay1 = __fmaf_rn( 0.5f, p.w, p.y);
    float aA  = __fmul_rn(p.z, p.w);
    float tA  = __fmul_rn(__fsub_rn(t.z, t.x), __fsub_rn(t.w, t.y));
    float iw  = fmaxf(__fsub_rn(fminf(ax1, t.z), fmaxf(ax0, t.x)), 0.f);
    float ih  = fmaxf(__fsub_rn(fminf(ay1, t.w), fmaxf(ay0, t.y)), 0.f);
    float inter = __fmul_rn(iw, ih);
    if (inter <= 0.f) return 0.f;
    return __fdividef(inter, __fsub_rn(__fadd_rn(tA, aA), inter));
}

// Decoded-box IoU, _rn-pinned (kAN record gate vs kD recompute must agree).
__device__ __forceinline__ float fiou_rn(const float4 t, float tA,
                                         float bx0, float by0, float bx1, float by1, float bA) {
    float iw = fmaxf(__fsub_rn(fminf(t.z, bx1), fmaxf(t.x, bx0)), 0.f);
    float ih = fmaxf(__fsub_rn(fminf(t.w, by1), fmaxf(t.y, by0)), 0.f);
    float inter = __fmul_rn(iw, ih);
    if (inter <= 0.f) return 0.f;
    return __fdividef(inter, __fsub_rn(__fadd_rn(tA, bA), inter));
}

__device__ __forceinline__ float fastrcp(float s) {
    float r = __uint_as_float(0x7EF311C3u - __float_as_uint(s));
    r = r * (2.f - s * r);
    r = r * (2.f - s * r);
    r = r * (2.f - s * r);
    return r;
}

// sigmoid(x)^2 * softplus(x): 2 MUFU (EX2 + LG2)
__device__ __forceinline__ float negterm(float x) {
    float e = __expf(x);
    float s = 1.f + e;
    float p = e * fastrcp(s);
    return p * p * __logf(s);
}

__device__ __forceinline__ float sl1(float v) {
    float av = fabsf(v);
    return (av < 0.11f) ? 4.5454545454545450f * v * v : av - 0.055f;
}

__device__ __forceinline__ float blockReduceSum(float v) {
    __shared__ float s[32];
    int lane = threadIdx.x & 31, wid = threadIdx.x >> 5;
    #pragma unroll
    for (int o = 16; o; o >>= 1) v += __shfl_down_sync(0xffffffffu, v, o);
    if (lane == 0) s[wid] = v;
    __syncthreads();
    int nw = (blockDim.x + 31) >> 5;
    v = (threadIdx.x < nw) ? s[threadIdx.x] : 0.f;
    if (wid == 0) {
        #pragma unroll
        for (int o = 16; o; o >>= 1) v += __shfl_down_sync(0xffffffffu, v, o);
    }
    return v; // valid in thread 0
}

// ------------------------------ kernels ---------------------------------
__global__ void kI() {
    size_t i = (size_t)blockIdx.x * blockDim.x + threadIdx.x;
    uint4* h4 = (uint4*)g_hist;
    const size_t n4 = (size_t)B * G * NBINS / 4;
    if (i < n4) h4[i] = make_uint4(0u, 0u, 0u, 0u);
    if (i < B * G) { g_maxiou[i] = 0u; g_lcnt[i] = 0; }
    if (i == 0) { g_sums[0] = 0.0; g_sums[1] = 0.0; g_nrec = 0; g_anyfb = 0; }
}

// Fused: blocks [0,KA_BLOCKS) = per-anchor pass (hist + candidate list + t2 max
//        + sparse records); rest = dense negative loss over logits.
__global__ void kAN(const float4* __restrict__ br, const float4* __restrict__ anc,
                    const float4* __restrict__ tbx, const float4* __restrict__ logits4) {
    if (blockIdx.x < KA_BLOCKS) {
        int b = blockIdx.x >> 8;
        int a = ((blockIdx.x & 255) << 8) | threadIdx.x;
        __shared__ float4 st[G];
        __shared__ float  sta[G];
        __shared__ unsigned smax[G];
        if (threadIdx.x < G) {
            float4 t = tbx[b * G + threadIdx.x];
            st[threadIdx.x] = t;
            sta[threadIdx.x] = __fmul_rn(__fsub_rn(t.z, t.x), __fsub_rn(t.w, t.y));
            smax[threadIdx.x] = 0u;
        }
        __syncthreads();

        float4 l = br[b * A + a];
        float4 p = anc[a];
        float dcx = p.x + l.x * 0.1f * p.z;
        float dcy = p.y + l.y * 0.1f * p.w;
        float dw  = p.z * __expf(l.z * 0.2f);
        float dh  = p.w * __expf(l.w * 0.2f);
        float dx0 = dcx - 0.5f * dw, dy0 = dcy - 0.5f * dh;
        float dx1 = dcx + 0.5f * dw, dy1 = dcy + 0.5f * dh;
        float dA  = dw * dh;

        size_t hbase = (size_t)(b * G) * NBINS;
        float dmax = 0.f;
        #pragma unroll
        for (int g = 0; g < G; g++) {
            float4 t = st[g];
            float mi = anchor_iou(p, t);
            if (mi > 0.f) {
                unsigned bits = __float_as_uint(mi);
                unsigned bin = bits >> BSHIFT;
                atomicAdd(&g_hist[hbase + (size_t)g * NBINS + bin], 1u);
                if ((int)bin >= FLOORBIN) {     // candidate list push (superset of top-50)
                    int bg = b * G + g;
                    int pos = atomicAdd(&g_lcnt[bg], 1);
                    if (pos < CAP)
                        g_list[(size_t)bg * CAP + pos] =
                            ((unsigned long long)bits << 32) | (unsigned)(~(unsigned)a);
                }
            }
            float di = fiou_rn(t, sta[g], dx0, dy0, dx1, dy1, dA);
            dmax = fmaxf(dmax, di);
            unsigned db = __float_as_uint(di);
            if (db > smax[g]) atomicMax(&smax[g], db);
        }
        if (dmax > 0.49f) {
            int pos = atomicAdd(&g_nrec, 1);
            g_rec[pos] = ((unsigned)b << 16) | (unsigned)a;
        }
        __syncthreads();
        if (threadIdx.x < G) atomicMax(&g_maxiou[b * G + threadIdx.x], smax[threadIdx.x]);
    } else {
        const int n4 = B * A * C / 4;
        int bid = blockIdx.x - KA_BLOCKS;
        float acc = 0.f;
        for (int i = bid * blockDim.x + threadIdx.x; i < n4; i += KN_BLOCKS * blockDim.x) {
            float4 v = logits4[i];
            acc += negterm(v.x) + negterm(v.y) + negterm(v.z) + negterm(v.w);
        }
        float tot = blockReduceSum(acc);
        if (threadIdx.x == 0) atomicAdd(&g_sums[1], (double)tot);
    }
}

// Threshold per (b,g): largest suffix bin with count >= TOPK; invden; fallback flags
__global__ void kT() {
    int bg = blockIdx.x;
    const unsigned* h = g_hist + (size_t)bg * NBINS;
    __shared__ unsigned sb[NBINS];
    __shared__ unsigned sp[256];
    int t = threadIdx.x;
    unsigned acc = 0;
    #pragma unroll 4
    for (int i = 0; i < NBINS / 256; i++) {
        unsigned v = h[t * (NBINS / 256) + i];
        sb[t * (NBINS / 256) + i] = v;
        acc += v;
    }
    sp[t] = acc;
    __syncthreads();
    if (t == 0) {
        int total = 0;
        for (int c = 0; c < 256; c++) total += (int)sp[c];
        int cum = 0, tb = 0;
        for (int c = 255; c >= 0; c--) {
            if (cum + (int)sp[c] >= TOPK) {
                int base = c * (NBINS / 256);
                for (int i = NBINS / 256 - 1; i >= 0; i--) {
                    cum += (int)sb[base + i];
                    if (cum >= TOPK) { tb = base + i; break; }
                }
                break;
            }
            cum += (int)sp[c];
        }
        g_tbin[bg] = tb;
        // fallback: floor too high, list overflow, or <TOPK positives (deficit)
        int fb = 0;
        if (tb < FLOORBIN || g_lcnt[bg] > CAP) fb = 1;
        if (total < TOPK) fb = 2;
        g_fb[bg] = fb;
        if (fb) { g_lcnt[bg] = 0; atomicOr(&g_anyfb, 1); }
        float m = __uint_as_float(g_maxiou[bg]);
        g_invden[bg] = (m > 0.5f) ? __fdividef(1.f, m - 0.5f) : 0.f;
    }
}

// blocks [0,KD_FB_BLOCKS): fallback rescan (normally exits immediately);
// rest: sparse negative-loss correction.
__global__ void kD(const float4* __restrict__ br, const float4* __restrict__ anc,
                   const float4* __restrict__ tbx, const int* __restrict__ lab,
                   const float* __restrict__ logits) {
    if (blockIdx.x < KD_FB_BLOCKS) {
        if (g_anyfb == 0) return;            // uniform read; near-zero cost normally
        int b = blockIdx.x >> 8;
        int a = ((blockIdx.x & 255) << 8) | threadIdx.x;
        __shared__ float4 st[G];
        __shared__ int stbin[G];
        __shared__ int sfb[G];
        if (threadIdx.x < G) {
            st[threadIdx.x] = tbx[b * G + threadIdx.x];
            stbin[threadIdx.x] = g_tbin[b * G + threadIdx.x];
            sfb[threadIdx.x] = g_fb[b * G + threadIdx.x];
        }
        __syncthreads();
        float4 p = anc[a];
        for (int g = 0; g < G; g++) {
            if (!sfb[g]) continue;
            float mi = anchor_iou(p, st[g]);          // bit-identical to kAN
            unsigned bits = (mi > 0.f) ? __float_as_uint(mi) : 0u;
            bool q = (mi > 0.f) && ((int)(bits >> BSHIFT) >= stbin[g]);
            if (sfb[g] == 2 && a < 128) q = true;     // deficit: guarantee >=50 keys
            if (q) {
                int bg = b * G + g;
                int pos = atomicAdd(&g_lcnt[bg], 1);
                if (pos < CAP)
                    g_list[(size_t)bg * CAP + pos] =
                        ((unsigned long long)bits << 32) | (unsigned)(~(unsigned)a);
            }
        }
    } else {
        __shared__ float4 st[B * G];
        __shared__ float  sta[B * G];
        __shared__ float  sinv[B * G];
        __shared__ int    slbl[B * G];
        __shared__ int    sfirst[B * G];
        if (threadIdx.x < B * G) {
            float4 t = tbx[threadIdx.x];
            st[threadIdx.x] = t;
            sta[threadIdx.x] = __fmul_rn(__fsub_rn(t.z, t.x), __fsub_rn(t.w, t.y));
            sinv[threadIdx.x] = g_invden[threadIdx.x];
            slbl[threadIdx.x] = lab[threadIdx.x];
        }
        __syncthreads();
        if (threadIdx.x < B * G) {
            int b = threadIdx.x >> 4, g = threadIdx.x & 15, f = 1;
            for (int j = 0; j < g; j++) if (slbl[b * G + j] == slbl[threadIdx.x]) f = 0;
            sfirst[threadIdx.x] = f;
        }
        __syncthreads();

        int nrec = g_nrec;
        int bid = blockIdx.x - KD_FB_BLOCKS;
        float corr = 0.f;
        for (int i = bid * blockDim.x + threadIdx.x; i < nrec; i += KD_SP_BLOCKS * blockDim.x) {
            unsigned rec = g_rec[i];
            int b = rec >> 16;
            int a = rec & 0xffff;
            float4 l = br[b * A + a];
            float4 p = anc[a];
            float dcx = p.x + l.x * 0.1f * p.z;
            float dcy = p.y + l.y * 0.1f * p.w;
            float dw  = p.z * __expf(l.z * 0.2f);
            float dh  = p.w * __expf(l.w * 0.2f);
            float dx0 = dcx - 0.5f * dw, dy0 = dcy - 0.5f * dh;
            float dx1 = dcx + 0.5f * dw, dy1 = dcy + 0.5f * dh;
            float dA  = dw * dh;
            float obp[G];
            #pragma unroll
            for (int g = 0; g < G; g++) {
                int bg = b * G + g;
                float di = fiou_rn(st[bg], sta[bg], dx0, dy0, dx1, dy1, dA);
                obp[g] = fminf(fmaxf((di - 0.5f) * sinv[bg], 0.f), 1.f);
            }
            #pragma unroll
            for (int g = 0; g < G; g++) {
                int bg = b * G + g;
                if (!sfirst[bg]) continue;
                float bp = obp[g];
                #pragma unroll
                for (int j = g + 1; j < G; j++)
                    if (slbl[b * G + j] == slbl[bg]) bp = fmaxf(bp, obp[j]);
                if (bp > 0.f) {
                    float xl = logits[((size_t)(b * A) + a) * C + slbl[bg]];
                    float pt = negterm(xl);               // cancels dense term exactly
                    float e = __expf(xl);
                    float pp = e * fastrcp(1.f + e);
                    float x = pp * (1.f - bp);
                    float xt = x * x * (-__logf(1.f - x));
                    corr += xt - pt;
                }
            }
        }
        float tot = blockReduceSum(corr);
        if (threadIdx.x == 0 && tot != 0.f) atomicAdd(&g_sums[1], (double)tot);
    }
}

// Filter candidate list by tbin, exact-rank top-50, positive bag loss.
__global__ void kS(const float4* __restrict__ br, const float4* __restrict__ anc,
                   const float4* __restrict__ tbx, const int* __restrict__ lab,
                   const float* __restrict__ logits) {
    int bg = blockIdx.x;
    int b = bg >> 4, g = bg & 15;
    __shared__ unsigned long long skey[SCAP];
    __shared__ unsigned ssel[TOPK];
    __shared__ float swv[TOPK], swl[TOPK];
    __shared__ int sfc, scount;
    int tbin = g_tbin[bg];
    int cnt = min(g_lcnt[bg], CAP);
    if (threadIdx.x == 0) { sfc = 0; scount = 0; }
    __syncthreads();
    const unsigned long long* lst = g_list + (size_t)bg * CAP;
    for (int i = threadIdx.x; i < cnt; i += blockDim.x) {
        unsigned long long k = lst[i];
        if ((int)(k >> (32 + BSHIFT)) >= tbin) {
            int p = atomicAdd(&sfc, 1);
            if (p < SCAP) skey[p] = k;
        }
    }
    __syncthreads();
    int fc = min(sfc, SCAP);
    for (int i = threadIdx.x; i < fc; i += blockDim.x) {
        unsigned long long k = skey[i];
        int r = 0;
        for (int j = 0; j < fc; j++) r += (skey[j] > k);
        if (r < TOPK) {
            int s = atomicAdd(&scount, 1);
            ssel[s] = ~(unsigned)(k & 0xffffffffu);
        }
    }
    __syncthreads();
    int n = scount;
    float4 t = tbx[b * G + g];
    if (threadIdx.x < n) {
        unsigned a = ssel[threadIdx.x];
        float4 p = anc[a];
        float4 l = br[(size_t)b * A + a];
        int lbl = lab[b * G + g];
        float xl = logits[((size_t)(b * A) + a) * C + lbl];
        float e = __expf(xl);
        float mcp = __fdividef(e, 1.f + e);
        float gx = __fdividef((t.x + t.z) * 0.5f - p.x, 0.1f * p.z);
        float gy = __fdividef((t.y + t.w) * 0.5f - p.y, 0.1f * p.w);
        float gw = __logf(__fdividef(t.z - t.x, p.z)) * 5.0f;
        float gh = __logf(__fdividef(t.w - t.y, p.w)) * 5.0f;
        float reg = 0.75f * (sl1(gx - l.x) + sl1(gy - l.y) + sl1(gw - l.z) + sl1(gh - l.w));
        float mbp = __expf(-reg);
        float li = mcp * mbp;
        float w = __fdividef(1.f, fmaxf(1.f - li, 1e-12f));
        swv[threadIdx.x] = w;
        swl[threadIdx.x] = w * li;
    }
    __syncthreads();
    if (threadIdx.x == 0 && n > 0) {
        float sw = 0.f, sl = 0.f;
        for (int i = 0; i < n; i++) { sw += swv[i]; sl += swl[i]; }
        float bag = __fdividef(sl, sw);
        atomicAdd(&g_sums[0], (double)(-__logf(bag)));
    }
}

__global__ void kF(float* out) {
    out[0] = (float)(g_sums[0] * (0.5 / 128.0));    // ALPHA / (B*G)
    out[1] = (float)(g_sums[1] * (0.5 / 6400.0));   // (1-ALPHA) / (B*G*TOPK)
}

// ------------------------------ launch -----------------------------------
extern "C" void kernel_launch(void* const* d_in, const int* in_sizes, int n_in,
                              void* d_out, int out_size) {
    const float4* br     = (const float4*)d_in[0];   // box_regression (B,A,4)
    const float*  logits = (const float*) d_in[1];   // cls_logits (B,A,C)
    const float4* anc    = (const float4*)d_in[2];   // anchors (A,4)
    const float4* tbx    = (const float4*)d_in[3];   // targets_boxes (B,G,4)
    const int*    lab    = (const int*)   d_in[4];   // labels (B,G)
    float* out = (float*)d_out;

    kI<<<1024, 256>>>();
    kAN<<<KA_BLOCKS + KN_BLOCKS, 256>>>(br, anc, tbx, (const float4*)logits);
    kT<<<B * G, 256>>>();
    kD<<<KD_FB_BLOCKS + KD_SP_BLOCKS, 256>>>(br, anc, tbx, lab, logits);
    kS<<<B * G, 256>>>(br, anc, tbx, lab, logits);
    kF<<<1, 1>>>(out);
}

// round 10
// speedup vs baseline: 1.8267x; 1.8267x over previous
#include <cuda_runtime.h>

#define B 8
#define A 65536
#define C 80
#define G 16
#define TOPK 50
#define NBINS 8192
#define BSHIFT 17
#define CAND 4096
#define KA_BLOCKS 2048
#define KN_BLOCKS 6144
#define KD_CAND_BLOCKS 2048
#define KD_SP_BLOCKS 256

// ------------------------- static device scratch -------------------------
__device__ unsigned g_hist[(size_t)B * G * NBINS];   // 4.2 MB histograms
__device__ unsigned g_maxiou[B * G];                 // max decoded IoU (bits)
__device__ unsigned g_thr[B * G];                    // threshold float bits (tbin<<17)
__device__ float    g_invden[B * G];                 // 1/(t2-0.5) or 0
__device__ int      g_ccnt[B * G];                   // candidate counts
__device__ unsigned g_cand[(size_t)B * G * CAND];    // candidate anchor ids
__device__ int      g_nrec;                          // sparse record count
__device__ unsigned g_rec[B * A];                    // sparse records (b<<16 | a)
__device__ double   g_sums[2];                       // [0]=pos, [1]=neg

// ------------------------------ helpers ---------------------------------
// Shared corner-form conversion + IoU. All kernels call exactly these ops in
// this order (_rn-pinned), so cross-kernel IoU values are bitwise identical.
struct Corners { float x0, y0, x1, y1, area; };

__device__ __forceinline__ Corners corners_rn(const float4 p) {
    Corners c;
    c.x0 = __fmaf_rn(-0.5f, p.z, p.x);
    c.y0 = __fmaf_rn(-0.5f, p.w, p.y);
    c.x1 = __fmaf_rn( 0.5f, p.z, p.x);
    c.y1 = __fmaf_rn( 0.5f, p.w, p.y);
    c.area = __fmul_rn(p.z, p.w);
    return c;
}

__device__ __forceinline__ float iou_ct(const Corners c, const float4 t, float tA) {
    float iw = fmaxf(__fsub_rn(fminf(c.x1, t.z), fmaxf(c.x0, t.x)), 0.f);
    float ih = fmaxf(__fsub_rn(fminf(c.y1, t.w), fmaxf(c.y0, t.y)), 0.f);
    float inter = __fmul_rn(iw, ih);
    if (inter <= 0.f) return 0.f;
    return __fdividef(inter, __fsub_rn(__fadd_rn(tA, c.area), inter));
}

// Decoded-box IoU, _rn-pinned (kAN record gate vs kD recompute must agree).
__device__ __forceinline__ float fiou_rn(const float4 t, float tA,
                                         float bx0, float by0, float bx1, float by1, float bA) {
    float iw = fmaxf(__fsub_rn(fminf(t.z, bx1), fmaxf(t.x, bx0)), 0.f);
    float ih = fmaxf(__fsub_rn(fminf(t.w, by1), fmaxf(t.y, by0)), 0.f);
    float inter = __fmul_rn(iw, ih);
    if (inter <= 0.f) return 0.f;
    return __fdividef(inter, __fsub_rn(__fadd_rn(tA, bA), inter));
}

__device__ __forceinline__ float fastrcp(float s) {
    float r = __uint_as_float(0x7EF311C3u - __float_as_uint(s));
    r = r * (2.f - s * r);
    r = r * (2.f - s * r);
    r = r * (2.f - s * r);
    return r;
}

// sigmoid(x)^2 * softplus(x): 2 MUFU (EX2 + LG2)
__device__ __forceinline__ float negterm(float x) {
    float e = __expf(x);
    float s = 1.f + e;
    float p = e * fastrcp(s);
    return p * p * __logf(s);
}

__device__ __forceinline__ float sl1(float v) {
    float av = fabsf(v);
    return (av < 0.11f) ? 4.5454545454545450f * v * v : av - 0.055f;
}

__device__ __forceinline__ float blockReduceSum(float v) {
    __shared__ float s[32];
    int lane = threadIdx.x & 31, wid = threadIdx.x >> 5;
    #pragma unroll
    for (int o = 16; o; o >>= 1) v += __shfl_down_sync(0xffffffffu, v, o);
    if (lane == 0) s[wid] = v;
    __syncthreads();
    int nw = (blockDim.x + 31) >> 5;
    v = (threadIdx.x < nw) ? s[threadIdx.x] : 0.f;
    if (wid == 0) {
        #pragma unroll
        for (int o = 16; o; o >>= 1) v += __shfl_down_sync(0xffffffffu, v, o);
    }
    return v; // valid in thread 0
}

// ------------------------------ kernels ---------------------------------
__global__ void kI() {
    size_t i = (size_t)blockIdx.x * blockDim.x + threadIdx.x;
    uint4* h4 = (uint4*)g_hist;
    const size_t n4 = (size_t)B * G * NBINS / 4;
    if (i < n4) h4[i] = make_uint4(0u, 0u, 0u, 0u);
    if (i < B * G) { g_maxiou[i] = 0u; g_ccnt[i] = 0; }
    if (i == 0) { g_sums[0] = 0.0; g_sums[1] = 0.0; g_nrec = 0; }
}

// Fused: blocks [0,KA_BLOCKS) = per-anchor pass (hist + t2 max + sparse records);
//        rest = dense negative loss over logits.
__global__ void kAN(const float4* __restrict__ br, const float4* __restrict__ anc,
                    const float4* __restrict__ tbx, const float4* __restrict__ logits4) {
    if (blockIdx.x < KA_BLOCKS) {
        int b = blockIdx.x >> 8;
        int a = ((blockIdx.x & 255) << 8) | threadIdx.x;
        __shared__ float4 st[G];
        __shared__ float  sta[G];
        __shared__ unsigned smax[G];
        if (threadIdx.x < G) {
            float4 t = tbx[b * G + threadIdx.x];
            st[threadIdx.x] = t;
            sta[threadIdx.x] = __fmul_rn(__fsub_rn(t.z, t.x), __fsub_rn(t.w, t.y));
            smax[threadIdx.x] = 0u;
        }
        __syncthreads();

        float4 l = br[b * A + a];
        float4 p = anc[a];
        Corners ac = corners_rn(p);              // hoisted: once per anchor
        float dcx = p.x + l.x * 0.1f * p.z;
        float dcy = p.y + l.y * 0.1f * p.w;
        float dw  = p.z * __expf(l.z * 0.2f);
        float dh  = p.w * __expf(l.w * 0.2f);
        float dx0 = dcx - 0.5f * dw, dy0 = dcy - 0.5f * dh;
        float dx1 = dcx + 0.5f * dw, dy1 = dcy + 0.5f * dh;
        float dA  = dw * dh;

        size_t hbase = (size_t)(b * G) * NBINS;
        float dmax = 0.f;
        #pragma unroll
        for (int g = 0; g < G; g++) {
            float4 t = st[g];
            float mi = iou_ct(ac, t, sta[g]);
            if (mi > 0.f)
                atomicAdd(&g_hist[hbase + (size_t)g * NBINS + (__float_as_uint(mi) >> BSHIFT)], 1u);
            float di = fiou_rn(t, sta[g], dx0, dy0, dx1, dy1, dA);
            dmax = fmaxf(dmax, di);
            unsigned db = __float_as_uint(di);
            if (db > smax[g]) atomicMax(&smax[g], db);   // read-filtered max
        }
        if (dmax > 0.49f) {                      // margin vs recompute drift
            int pos = atomicAdd(&g_nrec, 1);
            g_rec[pos] = ((unsigned)b << 16) | (unsigned)a;
        }
        __syncthreads();
        if (threadIdx.x < G) atomicMax(&g_maxiou[b * G + threadIdx.x], smax[threadIdx.x]);
    } else {
        const int n4 = B * A * C / 4;
        int bid = blockIdx.x - KA_BLOCKS;
        float acc = 0.f;
        for (int i = bid * blockDim.x + threadIdx.x; i < n4; i += KN_BLOCKS * blockDim.x) {
            float4 v = logits4[i];
            acc += negterm(v.x) + negterm(v.y) + negterm(v.z) + negterm(v.w);
        }
        float tot = blockReduceSum(acc);
        if (threadIdx.x == 0) atomicAdd(&g_sums[1], (double)tot);
    }
}

// Threshold per (b,g): largest suffix bin with count >= TOPK; invden
__global__ void kT() {
    int bg = blockIdx.x;
    const unsigned* h = g_hist + (size_t)bg * NBINS;
    __shared__ unsigned sb[NBINS];
    __shared__ unsigned sp[256];
    int t = threadIdx.x;
    unsigned acc = 0;
    #pragma unroll 4
    for (int i = 0; i < NBINS / 256; i++) {
        unsigned v = h[t * (NBINS / 256) + i];
        sb[t * (NBINS / 256) + i] = v;
        acc += v;
    }
    sp[t] = acc;
    __syncthreads();
    if (t == 0) {
        int cum = 0, tb = 0;
        for (int c = 255; c >= 0; c--) {
            if (cum + (int)sp[c] >= TOPK) {
                int base = c * (NBINS / 256);
                for (int i = NBINS / 256 - 1; i >= 0; i--) {
                    cum += (int)sb[base + i];
                    if (cum >= TOPK) { tb = base + i; break; }
                }
                break;
            }
            cum += (int)sp[c];
        }
        g_thr[bg] = (unsigned)tb << BSHIFT;      // min float bits of threshold bin
        float m = __uint_as_float(g_maxiou[bg]);
        g_invden[bg] = (m > 0.5f) ? __fdividef(1.f, m - 0.5f) : 0.f;
    }
}

// Fused post-threshold: blocks [0,KD_CAND_BLOCKS) = candidate scan
// (block = image b x 256-anchor chunk); rest = sparse neg-loss correction.
__global__ void kD(const float4* __restrict__ br, const float4* __restrict__ anc,
                   const float4* __restrict__ tbx, const int* __restrict__ lab,
                   const float* __restrict__ logits) {
    if (blockIdx.x < KD_CAND_BLOCKS) {
        int b = blockIdx.x >> 8;
        int a = ((blockIdx.x & 255) << 8) | threadIdx.x;
        __shared__ float4 st[G];
        __shared__ float  sta[G];
        __shared__ float  sthr[G];
        if (threadIdx.x < G) {
            float4 t = tbx[b * G + threadIdx.x];
            st[threadIdx.x] = t;
            sta[threadIdx.x] = __fmul_rn(__fsub_rn(t.z, t.x), __fsub_rn(t.w, t.y));
            sthr[threadIdx.x] = __uint_as_float(g_thr[b * G + threadIdx.x]);
        }
        __syncthreads();
        Corners ac = corners_rn(anc[a]);         // hoisted: once per anchor
        #pragma unroll
        for (int g = 0; g < G; g++) {
            float mi = iou_ct(ac, st[g], sta[g]); // bit-identical to kAN's value
            // (bits>>17) >= tbin  <=>  mi >= uint_as_float(tbin<<17), both positive
            if (mi > 0.f && mi >= sthr[g]) {
                int bg = b * G + g;
                int pos = atomicAdd(&g_ccnt[bg], 1);
                if (pos < CAND) g_cand[(size_t)bg * CAND + pos] = (unsigned)a;
            }
        }
    } else {
        __shared__ float4 st[B * G];
        __shared__ float  sta[B * G];
        __shared__ float  sinv[B * G];
        __shared__ int    slbl[B * G];
        __shared__ int    sfirst[B * G];
        if (threadIdx.x < B * G) {
            float4 t = tbx[threadIdx.x];
            st[threadIdx.x] = t;
            sta[threadIdx.x] = __fmul_rn(__fsub_rn(t.z, t.x), __fsub_rn(t.w, t.y));
            sinv[threadIdx.x] = g_invden[threadIdx.x];
            slbl[threadIdx.x] = lab[threadIdx.x];
        }
        __syncthreads();
        if (threadIdx.x < B * G) {
            int b = threadIdx.x >> 4, g = threadIdx.x & 15, f = 1;
            for (int j = 0; j < g; j++) if (slbl[b * G + j] == slbl[threadIdx.x]) f = 0;
            sfirst[threadIdx.x] = f;
        }
        __syncthreads();

        int nrec = g_nrec;
        int bid = blockIdx.x - KD_CAND_BLOCKS;
        float corr = 0.f;
        for (int i = bid * blockDim.x + threadIdx.x; i < nrec; i += KD_SP_BLOCKS * blockDim.x) {
            unsigned rec = g_rec[i];
            int b = rec >> 16;
            int a = rec & 0xffff;
            float4 l = br[b * A + a];
            float4 p = anc[a];
            float dcx = p.x + l.x * 0.1f * p.z;
            float dcy = p.y + l.y * 0.1f * p.w;
            float dw  = p.z * __expf(l.z * 0.2f);
            float dh  = p.w * __expf(l.w * 0.2f);
            float dx0 = dcx - 0.5f * dw, dy0 = dcy - 0.5f * dh;
            float dx1 = dcx + 0.5f * dw, dy1 = dcy + 0.5f * dh;
            float dA  = dw * dh;
            float obp[G];
            #pragma unroll
            for (int g = 0; g < G; g++) {
                int bg = b * G + g;
                float di = fiou_rn(st[bg], sta[bg], dx0, dy0, dx1, dy1, dA);
                obp[g] = fminf(fmaxf((di - 0.5f) * sinv[bg], 0.f), 1.f);
            }
            #pragma unroll
            for (int g = 0; g < G; g++) {
                int bg = b * G + g;
                if (!sfirst[bg]) continue;
                float bp = obp[g];
                #pragma unroll
                for (int j = g + 1; j < G; j++)
                    if (slbl[b * G + j] == slbl[bg]) bp = fmaxf(bp, obp[j]);
                if (bp > 0.f) {
                    float xl = logits[((size_t)(b * A) + a) * C + slbl[bg]];
                    float pt = negterm(xl);               // cancels dense term exactly
                    float e = __expf(xl);
                    float pp = e * fastrcp(1.f + e);
                    float x = pp * (1.f - bp);
                    float xt = x * x * (-__logf(1.f - x));
                    corr += xt - pt;
                }
            }
        }
        float tot = blockReduceSum(corr);
        if (threadIdx.x == 0 && tot != 0.f) atomicAdd(&g_sums[1], (double)tot);
    }
}

// Exact top-50 select (recompute exact mqm per candidate) + positive bag loss
__global__ void kS(const float4* __restrict__ br, const float4* __restrict__ anc,
                   const float4* __restrict__ tbx, const int* __restrict__ lab,
                   const float* __restrict__ logits) {
    int bg = blockIdx.x;
    int b = bg >> 4, g = bg & 15;
    __shared__ unsigned long long skey[CAND];
    __shared__ unsigned ssel[TOPK];
    __shared__ float swv[TOPK], swl[TOPK];
    __shared__ int scount;
    float4 t = tbx[b * G + g];
    float tA = __fmul_rn(__fsub_rn(t.z, t.x), __fsub_rn(t.w, t.y));
    int cnt = min(g_ccnt[bg], CAND);
    for (int i = threadIdx.x; i < cnt; i += blockDim.x) {
        unsigned a = g_cand[(size_t)bg * CAND + i];
        Corners ac = corners_rn(anc[a]);
        float mi = iou_ct(ac, t, tA);            // bit-identical across kernels
        skey[i] = ((unsigned long long)__float_as_uint(mi) << 32) | (unsigned)(~a);
    }
    if (threadIdx.x == 0) scount = 0;
    __syncthreads();
    for (int i = threadIdx.x; i < cnt; i += blockDim.x) {
        unsigned long long k = skey[i];
        int r = 0;
        for (int j = 0; j < cnt; j++) r += (skey[j] > k);
        if (r < TOPK) {
            int s = atomicAdd(&scount, 1);
            ssel[s] = ~(unsigned)(k & 0xffffffffu);
        }
    }
    __syncthreads();
    int n = scount;
    if (threadIdx.x < n) {
        unsigned a = ssel[threadIdx.x];
        float4 p = anc[a];
        float4 l = br[(size_t)b * A + a];
        int lbl = lab[b * G + g];
        float xl = logits[((size_t)(b * A) + a) * C + lbl];
        float e = __expf(xl);
        float mcp = __fdividef(e, 1.f + e);
        float gx = __fdividef((t.x + t.z) * 0.5f - p.x, 0.1f * p.z);
        float gy = __fdividef((t.y + t.w) * 0.5f - p.y, 0.1f * p.w);
        float gw = __logf(__fdividef(t.z - t.x, p.z)) * 5.0f;
        float gh = __logf(__fdividef(t.w - t.y, p.w)) * 5.0f;
        float reg = 0.75f * (sl1(gx - l.x) + sl1(gy - l.y) + sl1(gw - l.z) + sl1(gh - l.w));
        float mbp = __expf(-reg);
        float li = mcp * mbp;
        float w = __fdividef(1.f, fmaxf(1.f - li, 1e-12f));
        swv[threadIdx.x] = w;
        swl[threadIdx.x] = w * li;
    }
    __syncthreads();
    if (threadIdx.x == 0 && n > 0) {
        float sw = 0.f, sl = 0.f;
        for (int i = 0; i < n; i++) { sw += swv[i]; sl += swl[i]; }
        float bag = __fdividef(sl, sw);
        atomicAdd(&g_sums[0], (double)(-__logf(bag)));
    }
}

__global__ void kF(float* out) {
    out[0] = (float)(g_sums[0] * (0.5 / 128.0));    // ALPHA / (B*G)
    out[1] = (float)(g_sums[1] * (0.5 / 6400.0));   // (1-ALPHA) / (B*G*TOPK)
}

// ------------------------------ launch -----------------------------------
extern "C" void kernel_launch(void* const* d_in, const int* in_sizes, int n_in,
                              void* d_out, int out_size) {
    const float4* br     = (const float4*)d_in[0];   // box_regression (B,A,4)
    const float*  logits = (const float*) d_in[1];   // cls_logits (B,A,C)
    const float4* anc    = (const float4*)d_in[2];   // anchors (A,4)
    const float4* tbx    = (const float4*)d_in[3];   // targets_boxes (B,G,4)
    const int*    lab    = (const int*)   d_in[4];   // labels (B,G)
    float* out = (float*)d_out;

    kI<<<1024, 256>>>();
    kAN<<<KA_BLOCKS + KN_BLOCKS, 256>>>(br, anc, tbx, (const float4*)logits);
    kT<<<B * G, 256>>>();
    kD<<<KD_CAND_BLOCKS + KD_SP_BLOCKS, 256>>>(br, anc, tbx, lab, logits);
    kS<<<B * G, 256>>>(br, anc, tbx, lab, logits);
    kF<<<1, 1>>>(out);
}